// round 1
// baseline (speedup 1.0000x reference)
#include <cuda_runtime.h>

namespace {
constexpr int PNP = 4;                 // num_pumps
constexpr int MOD = 4;                 // modes
constexpr int NCH = 100;               // num_channels
constexpr int F   = NCH + PNP;         // 104 frequencies
constexpr int FM  = F * MOD;           // 416 state entries
constexpr int XW  = PNP * (1 + MOD);   // 20 floats per batch row of x
constexpr int NT  = 128;               // threads per block
constexpr float C0F   = 299792458.0f;
constexpr float ALPHA = 2.3025850929940457e-4f;  // 1e-3*ln(10)/10
}

// Q[j*4+mi] = sum_mj overlap[mi][mj] * Pk[j*4+mj]
#define DO_QCOMP()                                                      \
  for (int u = t; u < FM; u += NT) {                                    \
    const float* pj = Pk + (u & ~3);                                    \
    const float* om = ov + ((u & 3) << 2);                              \
    Q[u] = om[0]*pj[0] + om[1]*pj[1] + om[2]*pj[2] + om[3]*pj[3];       \
  }                                                                     \
  __syncthreads();

// k_m = (sum_j gainT[j][i]*Q[j][m] - loss_m) * Pk[4i+m]
#define DO_MATVEC(k0,k1,k2,k3)                                          \
  float k0, k1, k2, k3;                                                 \
  {                                                                     \
    float a0=0.f, a1=0.f, a2=0.f, a3=0.f;                               \
    const float*  gp = gainT + i;                                       \
    const float4* qp = (const float4*)Q;                                \
    _Pragma("unroll 8")                                                 \
    for (int j = 0; j < F; ++j) {                                       \
      const float  g = gp[j*F];                                         \
      const float4 q = qp[j];                                           \
      a0 = fmaf(g, q.x, a0); a1 = fmaf(g, q.y, a1);                     \
      a2 = fmaf(g, q.z, a2); a3 = fmaf(g, q.w, a3);                     \
    }                                                                   \
    k0 = (a0 - l0) * Pk[4*i+0];                                         \
    k1 = (a1 - l1) * Pk[4*i+1];                                         \
    k2 = (a2 - l2) * Pk[4*i+2];                                         \
    k3 = (a3 - l3) * Pk[4*i+3];                                         \
  }

__global__ __launch_bounds__(NT, 4) void raman_kernel(
    const float* __restrict__ x,
    const float* __restrict__ sig_freq,
    const float* __restrict__ sig_pow,
    const float* __restrict__ sig_loss,
    const float* __restrict__ lcoef,
    const float* __restrict__ overlap,
    const float* __restrict__ raman,
    const int*   __restrict__ steps_p,
    const float* __restrict__ length_p,
    const float* __restrict__ maxf_p,
    int Lr,
    float* __restrict__ out)
{
    extern __shared__ float sm[];
    float* gainT = sm;               // F*F floats, gainT[j*F+i] = gain[i][j]
    float* Q     = gainT + F*F;      // FM (16B aligned: F*F*4 = 43264)
    float* Pc    = Q  + FM;          // state at step start
    float* Pk    = Pc + FM;          // stage input
    float* acc   = Pk + FM;          // k1 + 2k2 + 2k3
    float* lossv = acc + FM;         // FM
    float* ov    = lossv + FM;       // 16 (overlap)
    float* freqs = ov + 16;          // F

    const int b = blockIdx.x;
    const int t = threadIdx.x;
    const float* xb = x + b * XW;

    const int   steps  = *steps_p;
    const float length = *length_p;
    const float maxf   = *maxf_p;
    const float h  = length / (float)(steps - 1);
    const float h2 = 0.5f * h;
    const float h6 = h * (1.0f / 6.0f);

    if (t < 16) ov[t] = overlap[t];
    for (int u = t; u < F; u += NT)
        freqs[u] = (u < PNP) ? (C0F / xb[u]) : sig_freq[u - PNP];

    const float lc0 = lcoef[0], lc1 = lcoef[1], lc2 = lcoef[2];
    for (int u = t; u < FM; u += NT) {
        float lv, pv;
        if (u < PNP * MOD) {
            float wn = xb[u >> 2] * 1e9f;
            lv = (lc2 + lc1 * wn + lc0 * wn * wn) * ALPHA;
            pv = xb[PNP + u];
        } else {
            lv = sig_loss[u - PNP * MOD];
            pv = sig_pow[u - PNP * MOD];
        }
        lossv[u] = lv; Pc[u] = pv; Pk[u] = pv;
    }
    __syncthreads();

    // ---- per-batch 104x104 gain matrix (transposed store) ----
    {
        const float scale = (float)(Lr - 1) / maxf;
        for (int idx = t; idx < F * F; idx += NT) {
            const int ii = idx / F;
            const int jj = idx - ii * F;
            const float fi = freqs[ii], fj = freqs[jj];
            const float fd = fj - fi;
            const float pos = fabsf(fd) * scale;
            int i0 = (int)floorf(pos);
            i0 = min(max(i0, 0), Lr - 2);
            const float w = pos - (float)i0;
            float g = raman[i0] * (1.0f - w) + raman[i0 + 1] * w;
            if (fd < 0.0f) g = -g;
            g *= fmaxf(1.0f, fi / fj);
            gainT[jj * F + ii] = g;
        }
    }
    __syncthreads();

    const int  i     = t;
    const bool rowok = (i < F);
    const float l0 = rowok ? lossv[4*i+0] : 0.f;
    const float l1 = rowok ? lossv[4*i+1] : 0.f;
    const float l2 = rowok ? lossv[4*i+2] : 0.f;
    const float l3 = rowok ? lossv[4*i+3] : 0.f;

    for (int s = 0; s < steps - 1; ++s) {
        {   // stage 1: k1 = ode(P)
            DO_QCOMP();
            if (rowok) {
                DO_MATVEC(k0, k1, k2, k3);
                acc[4*i+0] = k0; acc[4*i+1] = k1;
                acc[4*i+2] = k2; acc[4*i+3] = k3;
                Pk[4*i+0] = fmaf(h2, k0, Pc[4*i+0]);
                Pk[4*i+1] = fmaf(h2, k1, Pc[4*i+1]);
                Pk[4*i+2] = fmaf(h2, k2, Pc[4*i+2]);
                Pk[4*i+3] = fmaf(h2, k3, Pc[4*i+3]);
            }
            __syncthreads();
        }
        {   // stage 2: k2 = ode(P + h/2 k1)
            DO_QCOMP();
            if (rowok) {
                DO_MATVEC(k0, k1, k2, k3);
                acc[4*i+0] += 2.f*k0; acc[4*i+1] += 2.f*k1;
                acc[4*i+2] += 2.f*k2; acc[4*i+3] += 2.f*k3;
                Pk[4*i+0] = fmaf(h2, k0, Pc[4*i+0]);
                Pk[4*i+1] = fmaf(h2, k1, Pc[4*i+1]);
                Pk[4*i+2] = fmaf(h2, k2, Pc[4*i+2]);
                Pk[4*i+3] = fmaf(h2, k3, Pc[4*i+3]);
            }
            __syncthreads();
        }
        {   // stage 3: k3 = ode(P + h/2 k2)
            DO_QCOMP();
            if (rowok) {
                DO_MATVEC(k0, k1, k2, k3);
                acc[4*i+0] += 2.f*k0; acc[4*i+1] += 2.f*k1;
                acc[4*i+2] += 2.f*k2; acc[4*i+3] += 2.f*k3;
                Pk[4*i+0] = fmaf(h, k0, Pc[4*i+0]);
                Pk[4*i+1] = fmaf(h, k1, Pc[4*i+1]);
                Pk[4*i+2] = fmaf(h, k2, Pc[4*i+2]);
                Pk[4*i+3] = fmaf(h, k3, Pc[4*i+3]);
            }
            __syncthreads();
        }
        {   // stage 4: k4 = ode(P + h k3); P += h/6 (acc + k4)
            DO_QCOMP();
            if (rowok) {
                DO_MATVEC(k0, k1, k2, k3);
                float p0 = fmaf(h6, acc[4*i+0] + k0, Pc[4*i+0]);
                float p1 = fmaf(h6, acc[4*i+1] + k1, Pc[4*i+1]);
                float p2 = fmaf(h6, acc[4*i+2] + k2, Pc[4*i+2]);
                float p3 = fmaf(h6, acc[4*i+3] + k3, Pc[4*i+3]);
                Pc[4*i+0] = p0; Pk[4*i+0] = p0;
                Pc[4*i+1] = p1; Pk[4*i+1] = p1;
                Pc[4*i+2] = p2; Pk[4*i+2] = p2;
                Pc[4*i+3] = p3; Pk[4*i+3] = p3;
            }
            __syncthreads();
        }
    }

    // output: drop pump rows -> (B, NCH, MOD)
    for (int u = t; u < NCH * MOD; u += NT)
        out[b * (NCH * MOD) + u] = Pc[PNP * MOD + u];
}

extern "C" void kernel_launch(void* const* d_in, const int* in_sizes, int n_in,
                              void* d_out, int out_size) {
    const float* x        = (const float*)d_in[0];
    const float* sig_freq = (const float*)d_in[1];
    const float* sig_pow  = (const float*)d_in[2];
    const float* sig_loss = (const float*)d_in[3];
    const float* lcoef    = (const float*)d_in[4];
    const float* overlap  = (const float*)d_in[5];
    const float* raman    = (const float*)d_in[6];
    const int*   steps_p  = (const int*)d_in[10];
    const float* length_p = (const float*)d_in[11];
    const float* maxf_p   = (const float*)d_in[12];

    const int B  = in_sizes[0] / XW;
    const int Lr = in_sizes[6];

    const size_t smem = (size_t)(F * F + 5 * FM + 16 + F) * sizeof(float); // 52064 B
    cudaFuncSetAttribute(raman_kernel,
                         cudaFuncAttributeMaxDynamicSharedMemorySize, (int)smem);

    raman_kernel<<<B, NT, smem>>>(x, sig_freq, sig_pow, sig_loss, lcoef, overlap,
                                  raman, steps_p, length_p, maxf_p, Lr,
                                  (float*)d_out);
}